// round 16
// baseline (speedup 1.0000x reference)
#include <cuda_runtime.h>
#include <math_constants.h>

#define NB 64
#define NA 5
#define NC 20
#define NH 38
#define NW 38
#define HW (NH*NW)            // 1444
#define MAXB 50
#define RPB 2
#define GX (NH/RPB)           // 19
#define TPB 96
#define NACT 95               // threads 0..94: (col-pair major), 2x2 cells each
#define NBLK (GX*NB)          // 1216

__constant__ float c_aw[5] = {1.3221f, 3.19275f, 5.05587f, 9.47112f, 11.2364f};
__constant__ float c_ah[5] = {1.73145f, 4.00944f, 8.09892f, 4.84053f, 10.0071f};

// per-warp column bands (cells): warp0 cols 0-13, warp1 12-25, warp2 24-37
__constant__ float c_bandL[3] = {0.f, 12.f, 24.f};
__constant__ float c_bandR[3] = {14.f, 26.f, 38.f};   // R+1 of last cell

__device__ double             g_part[GX];
__device__ unsigned long long g_ctr;     // monotone across replays, never reset

__device__ __forceinline__ float fsig(float v){     // MUFU.TANH-based sigmoid
  return fmaf(__tanhf(0.5f*v), 0.5f, 0.5f);
}

// ---------------------------------------------------------------------------
// R12 structure with warp-banded candidate lists:
// lanes are COL-PAIR MAJOR so each warp owns a contiguous column band; Phase A
// builds one candidate sublist per warp using the exact x-window
// |px-gx| < 0.4*gw (same derivation as the y-band). Hot loop unchanged, just
// shorter (n ~9 -> ~4) with zero per-iteration tests.
// ---------------------------------------------------------------------------
__global__ void __launch_bounds__(TPB, 8) region_kernel(const float* __restrict__ out,
                                                        const float* __restrict__ tgt,
                                                        float* __restrict__ res){
  const int b   = blockIdx.y;
  const int j0  = blockIdx.x * RPB;
  const int tid = threadIdx.x;
  const int lane = tid & 31;
  const int wid  = tid >> 5;

  __shared__ float4 s_cb [3][MAXB+1];  // per-warp candidates (+1 pad)
  __shared__ float  s_ncg[3][MAXB+1];  // per-warp -0.375*areaG (+1 pad)
  __shared__ int    s_ncw[3];
  __shared__ int    s_akey[MAXB];
  __shared__ int    s_at[MAXB];
  __shared__ float4 s_aA[MAXB];        // txv, tyv, gw, gh
  __shared__ float4 s_aB[MAXB];        // gxl, gxh, gyl, gyh
  __shared__ float  s_acl[MAXB];       // gcls
  __shared__ int    s_na, s_w0all, s_islast;
  __shared__ float  s_ws[TPB/32];

  if (tid < 3) s_ncw[tid] = 0;
  if (tid == 0) s_na = 0;

  // ---- tgt load + ballot prefix-AND validity (warps 0-1) ----
  float gcls=0.f, gx=0.f, gy=0.f, gw=0.f, gh=0.f, xn=1.0f;
  if (tid < MAXB){
    const float* p = tgt + b*(MAXB*5) + tid*5;
    gcls = p[0]; xn = p[1];
    gx = xn*(float)NW; gy = p[2]*(float)NH; gw = p[3]*(float)NW; gh = p[4]*(float)NH;
  }
  unsigned msk  = __ballot_sync(0xffffffffu, xn != 0.0f);
  unsigned need = 0xffffffffu >> (31 - lane);
  int      pre  = ((msk & need) == need);
  if (tid == 0) s_w0all = (msk == 0xffffffffu);

  // ---- thread -> (col pair major): a0 = ct%5, i0 = 2*(ct/5) ----
  const int ct = (tid < NACT) ? tid : (NACT-1);   // dup lane masked later
  const int a0 = ct % 5;
  const int i0 = (ct / 5) * 2;
  const int base = ((b*NA + a0)*25)*HW + j0*NW + i0;

  // ---- 10x LDG.64 prefetch before the barrier ----
  float2 r0c0 = *(const float2*)(out + base);
  float2 r0c1 = *(const float2*)(out + base +   HW);
  float2 r0c2 = *(const float2*)(out + base + 2*HW);
  float2 r0c3 = *(const float2*)(out + base + 3*HW);
  float2 r0c4 = *(const float2*)(out + base + 4*HW);
  float2 r1c0 = *(const float2*)(out + base + NW);
  float2 r1c1 = *(const float2*)(out + base + NW +   HW);
  float2 r1c2 = *(const float2*)(out + base + NW + 2*HW);
  float2 r1c3 = *(const float2*)(out + base + NW + 3*HW);
  float2 r1c4 = *(const float2*)(out + base + NW + 4*HW);

  __syncthreads();

  // ---- Phase A: pure-ALU per-GT-box prep (warps 0-1) ----
  if (tid < MAXB){
    int valid = (tid < 32) ? pre : (pre & s_w0all);

    int best = 0; float bi = -1.0f, bu = 1.0f;
    #pragma unroll
    for (int a = 0; a < NA; ++a){
      float inter = fminf(gw, c_aw[a]) * fminf(gh, c_ah[a]);
      float uni   = gw*gh + c_aw[a]*c_ah[a] - inter;
      if (inter*bu > bi*uni){ bi = inter; bu = uni; best = a; }
    }

    int gi = min(max((int)gx, 0), NW-1);
    int gj = min(max((int)gy, 0), NH-1);

    // y-band (block rows) + per-warp x-band sublists
    if (valid && fabsf(gy - ((float)j0 + 1.0f)) <= 1.0f + 0.4001f*gh + 1e-3f){
      float mx = 0.4001f*gw + 1e-3f;
      #pragma unroll
      for (int w = 0; w < 3; ++w){
        if (gx > c_bandL[w] - mx && gx < c_bandR[w] + mx){
          int u = atomicAdd(&s_ncw[w], 1);
          s_cb [w][u] = make_float4(gx-0.5f*gw, gx+0.5f*gw, gy-0.5f*gh, gy+0.5f*gh);
          s_ncg[w][u] = -0.375f*gw*gh;
        }
      }
    }
    if (valid && (gj == j0 || gj == j0+1)){
      int u = atomicAdd(&s_na, 1);
      s_akey[u] = (best*NH + gj)*NW + gi;
      s_at[u]   = tid;
      s_aA[u]   = make_float4(gx - (float)gi, gy - (float)gj, gw, gh);
      s_aB[u]   = make_float4(gx-0.5f*gw, gx+0.5f*gw, gy-0.5f*gh, gy+0.5f*gh);
      s_acl[u]  = gcls;
    }
  }
  __syncthreads();

  // ---- per-cell raw values; cell k: 0=(j0,i0) 1=(j0,i0+1) 2=(j0+1,i0) 3=(j0+1,i0+1)
  float O0[4] = {r0c0.x, r0c0.y, r1c0.x, r1c0.y};
  float O1[4] = {r0c1.x, r0c1.y, r1c1.x, r1c1.y};
  float O2[4] = {r0c2.x, r0c2.y, r1c2.x, r1c2.y};
  float O3[4] = {r0c3.x, r0c3.y, r1c3.x, r1c3.y};
  float O4[4] = {r0c4.x, r0c4.y, r1c4.x, r1c4.y};
  const int CB[4] = {base, base+1, base+NW, base+NW+1};

  // ---- assignment lookup (max-t wins = last-valid-wins) ----
  int U[4] = {-1,-1,-1,-1};
  {
    const int key0 = (a0*NH + j0)*NW + i0;
    const int KEY[4] = {key0, key0+1, key0+NW, key0+NW+1};
    int TB[4] = {-1,-1,-1,-1};
    const int na = s_na;
    for (int u = 0; u < na; ++u){
      int k = s_akey[u], tt = s_at[u];
      #pragma unroll
      for (int q = 0; q < 4; ++q)
        if (k == KEY[q] && tt > TB[q]){ TB[q] = tt; U[q] = u; }
    }
  }

  // ---- bboxes for all 4 cells ----
  float XL[4], XH[4], YL[4], YH[4], CP[4], M[4];
  #pragma unroll
  for (int k = 0; k < 4; ++k){
    float ci = (float)(i0 + (k & 1));
    float cj = (float)(j0 + (k >> 1));
    float pw = __expf(O2[k])*c_aw[a0], ph = __expf(O3[k])*c_ah[a0];
    float px = fsig(O0[k]) + ci,       py = fsig(O1[k]) + cj;
    XL[k] = px - 0.5f*pw; XH[k] = px + 0.5f*pw;
    YL[k] = py - 0.5f*ph; YH[k] = py + 0.5f*ph;
    CP[k] = 0.375f*pw*ph;
    M[k]  = -CUDART_INF_F;
  }

  // ---- software-pipelined candidate loop over THIS WARP'S sublist ----
  {
    const float4* cb  = s_cb [wid];
    const float*  ncgp = s_ncg[wid];
    const int n = s_ncw[wid];
    if (n > 0){
      float4 qq = cb[0]; float ncg = ncgp[0];
      for (int t = 0; t < n; ++t){
        float4 qn = cb[t+1]; float ncgn = ncgp[t+1];   // padded: in-bounds
        #pragma unroll
        for (int k = 0; k < 4; ++k){
          float cw = fmaxf(fminf(XH[k], qq.y) - fmaxf(XL[k], qq.x), 0.f);
          float ch = fminf(YH[k], qq.w) - fmaxf(YL[k], qq.z);
          M[k] = fmaxf(M[k], fmaf(cw, ch, ncg));
        }
        qq = qn; ncg = ncgn;
      }
    }
  }

  // ---- epilogue per cell: recover sigmoids algebraically from the bbox ----
  float lsum = 0.0f;
  #pragma unroll
  for (int k = 0; k < 4; ++k){
    float ci = (float)(i0 + (k & 1));
    float cj = (float)(j0 + (k >> 1));
    float x  = fmaf(0.5f, XH[k] + XL[k], -ci);   // = sigmoid(O0[k])
    float y  = fmaf(0.5f, YH[k] + YL[k], -cj);   // = sigmoid(O1[k])
    float cf = fsig(O4[k]);
    float tx=0.5f, ty=0.5f, tw=0.f, th=0.f, tcf=0.f;
    float cs = (M[k] > CP[k]) ? 0.f : 1.f;
    int u = U[k];
    if (u >= 0){
      float4 A = s_aA[u]; float4 B = s_aB[u];
      tx = A.x; ty = A.y;
      tw = __logf(__fdividef(A.z, c_aw[a0]));
      th = __logf(__fdividef(A.w, c_ah[a0]));
      float pw = XH[k]-XL[k], ph = YH[k]-YL[k];
      float uw = fmaxf(XH[k], B.y) - fminf(XL[k], B.x);
      float uh = fmaxf(YH[k], B.w) - fminf(YL[k], B.z);
      float cw = pw + A.z - uw, ch = ph + A.w - uh;
      float inter = (cw <= 0.f || ch <= 0.f) ? 0.f : cw*ch;
      tcf = __fdividef(inter, pw*ph + A.z*A.w - inter);
      cs = 5.0f;
      int label = (int)s_acl[u];
      float lsel = out[CB[k] + (5+label)*HW];
      float se = 0.f;
      #pragma unroll
      for (int cc = 0; cc < NC; ++cc)
        se += __expf(out[CB[k] + (5+cc)*HW]);
      lsum += __logf(se) - lsel;
    }
    float dx=x-tx, dy=y-ty, dw=O2[k]-tw, dh=O3[k]-th, dc=cf-tcf;
    lsum += 0.5f*(dx*dx + dy*dy + dw*dw + dh*dh) + 0.5f*cs*dc*dc;
  }

  if (tid >= NACT) lsum = 0.0f;    // duplicate lane contributes nothing

  // ---- reduce + block-level finalize ----
  #pragma unroll
  for (int off = 16; off > 0; off >>= 1)
    lsum += __shfl_down_sync(0xffffffffu, lsum, off);
  if (lane == 0) s_ws[wid] = lsum;
  __syncthreads();

  if (tid == 0){
    float bs = 0.f;
    #pragma unroll
    for (int wv = 0; wv < TPB/32; ++wv) bs += s_ws[wv];
    atomicAdd(&g_part[blockIdx.x], (double)bs);
    __threadfence();
    unsigned long long v = atomicAdd(&g_ctr, 1ull);
    s_islast = ((v % (unsigned long long)NBLK) == (unsigned long long)(NBLK-1)) ? 1 : 0;
  }
  __syncthreads();

  if (s_islast && tid == 0){
    __threadfence();
    double tot = 0.0;
    for (int q = 0; q < GX; ++q){
      unsigned long long old = atomicExch((unsigned long long*)&g_part[q], 0ull);
      tot += __longlong_as_double((long long)old);
    }
    res[0] = (float)tot;
  }
}

extern "C" void kernel_launch(void* const* d_in, const int* in_sizes, int n_in,
                              void* d_out, int out_size){
  const float* outp = (const float*)d_in[0];
  const float* tgtp = (const float*)d_in[1];
  if (n_in >= 2 && in_sizes[0] < in_sizes[1]){
    const float* tmp = outp; outp = tgtp; tgtp = tmp;
  }
  region_kernel<<<dim3(GX, NB), TPB>>>(outp, tgtp, (float*)d_out);
}

// round 17
// speedup vs baseline: 1.3149x; 1.3149x over previous
#include <cuda_runtime.h>
#include <math_constants.h>

#define NB 64
#define NA 5
#define NC 20
#define NH 38
#define NW 38
#define HW (NH*NW)            // 1444
#define MAXB 50
#define RPB 2
#define GX (NH/RPB)           // 19
#define TPB 96
#define NACT 95               // threads 0..94: (anchor, col-pair), 2x2 cells each
#define NBLK (GX*NB)          // 1216

__constant__ float c_aw[5] = {1.3221f, 3.19275f, 5.05587f, 9.47112f, 11.2364f};
__constant__ float c_ah[5] = {1.73145f, 4.00944f, 8.09892f, 4.84053f, 10.0071f};

__device__ double             g_part[GX];
__device__ unsigned long long g_ctr;     // monotone across replays, never reset

__device__ __forceinline__ float fsig(float v){     // MUFU.TANH-based sigmoid
  return fmaf(__tanhf(0.5f*v), 0.5f, 0.5f);
}

// ---------------------------------------------------------------------------
// EXACT R12 structure (measured champion: 13.47us kernel) with ONE change:
// __launch_bounds__(96, 9) -> 9 blocks/SM (reg cap 75 vs 80 natural), so all
// 1216 blocks are co-resident: single wave, no low-occupancy tail.
// ---------------------------------------------------------------------------
__global__ void __launch_bounds__(TPB, 9) region_kernel(const float* __restrict__ out,
                                                        const float* __restrict__ tgt,
                                                        float* __restrict__ res){
  const int b   = blockIdx.y;
  const int j0  = blockIdx.x * RPB;
  const int tid = threadIdx.x;
  const int lane = tid & 31;

  __shared__ float4 s_cb[MAXB+1];   // candidates (xlo,xhi,ylo,yhi)  (+1 pad)
  __shared__ float  s_ncg[MAXB+1];  // -0.375*areaG                  (+1 pad)
  __shared__ int    s_akey[MAXB];
  __shared__ int    s_at[MAXB];
  __shared__ float4 s_aA[MAXB];     // txv, tyv, gw, gh
  __shared__ float4 s_aB[MAXB];     // gxl, gxh, gyl, gyh
  __shared__ float  s_acl[MAXB];    // gcls
  __shared__ int    s_nc, s_na, s_w0all, s_islast;
  __shared__ float  s_ws[TPB/32];

  if (tid == 0){ s_nc = 0; s_na = 0; }

  // ---- tgt load + ballot prefix-AND validity (warps 0-1) ----
  float gcls=0.f, gx=0.f, gy=0.f, gw=0.f, gh=0.f, xn=1.0f;
  if (tid < MAXB){
    const float* p = tgt + b*(MAXB*5) + tid*5;
    gcls = p[0]; xn = p[1];
    gx = xn*(float)NW; gy = p[2]*(float)NH; gw = p[3]*(float)NW; gh = p[4]*(float)NH;
  }
  unsigned msk  = __ballot_sync(0xffffffffu, xn != 0.0f);
  unsigned need = 0xffffffffu >> (31 - lane);
  int      pre  = ((msk & need) == need);
  if (tid == 0) s_w0all = (msk == 0xffffffffu);

  // ---- thread -> (anchor a0, col pair i0, rows j0/j0+1) ----
  const int ct = (tid < NACT) ? tid : (NACT-1);   // dup lane masked later
  const int a0 = ct / 19;
  const int i0 = (ct - a0*19) * 2;
  const int base = ((b*NA + a0)*25)*HW + j0*NW + i0;

  // ---- 10x LDG.64 prefetch before the barrier ----
  float2 r0c0 = *(const float2*)(out + base);
  float2 r0c1 = *(const float2*)(out + base +   HW);
  float2 r0c2 = *(const float2*)(out + base + 2*HW);
  float2 r0c3 = *(const float2*)(out + base + 3*HW);
  float2 r0c4 = *(const float2*)(out + base + 4*HW);
  float2 r1c0 = *(const float2*)(out + base + NW);
  float2 r1c1 = *(const float2*)(out + base + NW +   HW);
  float2 r1c2 = *(const float2*)(out + base + NW + 2*HW);
  float2 r1c3 = *(const float2*)(out + base + NW + 3*HW);
  float2 r1c4 = *(const float2*)(out + base + NW + 4*HW);

  __syncthreads();

  // ---- Phase A: pure-ALU per-GT-box prep (warps 0-1) ----
  if (tid < MAXB){
    int valid = (tid < 32) ? pre : (pre & s_w0all);

    int best = 0; float bi = -1.0f, bu = 1.0f;
    #pragma unroll
    for (int a = 0; a < NA; ++a){
      float inter = fminf(gw, c_aw[a]) * fminf(gh, c_ah[a]);
      float uni   = gw*gh + c_aw[a]*c_ah[a] - inter;
      if (inter*bu > bi*uni){ bi = inter; bu = uni; best = a; }
    }

    int gi = min(max((int)gx, 0), NW-1);
    int gj = min(max((int)gy, 0), NH-1);

    if (valid && fabsf(gy - ((float)j0 + 1.0f)) <= 1.0f + 0.4001f*gh + 1e-3f){
      int u = atomicAdd(&s_nc, 1);
      s_cb[u]  = make_float4(gx-0.5f*gw, gx+0.5f*gw, gy-0.5f*gh, gy+0.5f*gh);
      s_ncg[u] = -0.375f*gw*gh;
    }
    if (valid && (gj == j0 || gj == j0+1)){
      int u = atomicAdd(&s_na, 1);
      s_akey[u] = (best*NH + gj)*NW + gi;
      s_at[u]   = tid;
      s_aA[u]   = make_float4(gx - (float)gi, gy - (float)gj, gw, gh);
      s_aB[u]   = make_float4(gx-0.5f*gw, gx+0.5f*gw, gy-0.5f*gh, gy+0.5f*gh);
      s_acl[u]  = gcls;
    }
  }
  __syncthreads();

  // ---- per-cell raw values; cell k: 0=(j0,i0) 1=(j0,i0+1) 2=(j0+1,i0) 3=(j0+1,i0+1)
  float O0[4] = {r0c0.x, r0c0.y, r1c0.x, r1c0.y};
  float O1[4] = {r0c1.x, r0c1.y, r1c1.x, r1c1.y};
  float O2[4] = {r0c2.x, r0c2.y, r1c2.x, r1c2.y};
  float O3[4] = {r0c3.x, r0c3.y, r1c3.x, r1c3.y};
  float O4[4] = {r0c4.x, r0c4.y, r1c4.x, r1c4.y};
  const int CB[4] = {base, base+1, base+NW, base+NW+1};

  // ---- assignment lookup (max-t wins = last-valid-wins) ----
  int U[4] = {-1,-1,-1,-1};
  {
    const int key0 = (a0*NH + j0)*NW + i0;
    const int KEY[4] = {key0, key0+1, key0+NW, key0+NW+1};
    int TB[4] = {-1,-1,-1,-1};
    const int na = s_na;
    for (int u = 0; u < na; ++u){
      int k = s_akey[u], tt = s_at[u];
      #pragma unroll
      for (int q = 0; q < 4; ++q)
        if (k == KEY[q] && tt > TB[q]){ TB[q] = tt; U[q] = u; }
    }
  }

  // ---- bboxes for all 4 cells ----
  float XL[4], XH[4], YL[4], YH[4], CP[4], M[4];
  #pragma unroll
  for (int k = 0; k < 4; ++k){
    float ci = (float)(i0 + (k & 1));
    float cj = (float)(j0 + (k >> 1));
    float pw = __expf(O2[k])*c_aw[a0], ph = __expf(O3[k])*c_ah[a0];
    float px = fsig(O0[k]) + ci,       py = fsig(O1[k]) + cj;
    XL[k] = px - 0.5f*pw; XH[k] = px + 0.5f*pw;
    YL[k] = py - 0.5f*ph; YH[k] = py + 0.5f*ph;
    CP[k] = 0.375f*pw*ph;
    M[k]  = -CUDART_INF_F;
  }

  // ---- software-pipelined candidate loop (4 cells fused) ----
  const int n = s_nc;
  if (n > 0){
    float4 qq = s_cb[0]; float ncg = s_ncg[0];
    for (int t = 0; t < n; ++t){
      float4 qn = s_cb[t+1]; float ncgn = s_ncg[t+1];   // padded: in-bounds
      #pragma unroll
      for (int k = 0; k < 4; ++k){
        float cw = fmaxf(fminf(XH[k], qq.y) - fmaxf(XL[k], qq.x), 0.f);
        float ch = fminf(YH[k], qq.w) - fmaxf(YL[k], qq.z);
        M[k] = fmaxf(M[k], fmaf(cw, ch, ncg));
      }
      qq = qn; ncg = ncgn;
    }
  }

  // ---- epilogue per cell: recover sigmoids algebraically from the bbox ----
  float lsum = 0.0f;
  #pragma unroll
  for (int k = 0; k < 4; ++k){
    float ci = (float)(i0 + (k & 1));
    float cj = (float)(j0 + (k >> 1));
    float x  = fmaf(0.5f, XH[k] + XL[k], -ci);   // = sigmoid(O0[k])
    float y  = fmaf(0.5f, YH[k] + YL[k], -cj);   // = sigmoid(O1[k])
    float cf = fsig(O4[k]);
    float tx=0.5f, ty=0.5f, tw=0.f, th=0.f, tcf=0.f;
    float cs = (M[k] > CP[k]) ? 0.f : 1.f;
    int u = U[k];
    if (u >= 0){
      float4 A = s_aA[u]; float4 B = s_aB[u];
      tx = A.x; ty = A.y;
      tw = __logf(__fdividef(A.z, c_aw[a0]));
      th = __logf(__fdividef(A.w, c_ah[a0]));
      float pw = XH[k]-XL[k], ph = YH[k]-YL[k];
      float uw = fmaxf(XH[k], B.y) - fminf(XL[k], B.x);
      float uh = fmaxf(YH[k], B.w) - fminf(YL[k], B.z);
      float cw = pw + A.z - uw, ch = ph + A.w - uh;
      float inter = (cw <= 0.f || ch <= 0.f) ? 0.f : cw*ch;
      tcf = __fdividef(inter, pw*ph + A.z*A.w - inter);
      cs = 5.0f;
      int label = (int)s_acl[u];
      float lsel = out[CB[k] + (5+label)*HW];
      float se = 0.f;
      #pragma unroll
      for (int cc = 0; cc < NC; ++cc)
        se += __expf(out[CB[k] + (5+cc)*HW]);
      lsum += __logf(se) - lsel;
    }
    float dx=x-tx, dy=y-ty, dw=O2[k]-tw, dh=O3[k]-th, dc=cf-tcf;
    lsum += 0.5f*(dx*dx + dy*dy + dw*dw + dh*dh) + 0.5f*cs*dc*dc;
  }

  if (tid >= NACT) lsum = 0.0f;    // duplicate lane contributes nothing

  // ---- reduce + block-level finalize ----
  #pragma unroll
  for (int off = 16; off > 0; off >>= 1)
    lsum += __shfl_down_sync(0xffffffffu, lsum, off);
  if (lane == 0) s_ws[tid >> 5] = lsum;
  __syncthreads();

  if (tid == 0){
    float bs = 0.f;
    #pragma unroll
    for (int wv = 0; wv < TPB/32; ++wv) bs += s_ws[wv];
    atomicAdd(&g_part[blockIdx.x], (double)bs);
    __threadfence();
    unsigned long long v = atomicAdd(&g_ctr, 1ull);
    s_islast = ((v % (unsigned long long)NBLK) == (unsigned long long)(NBLK-1)) ? 1 : 0;
  }
  __syncthreads();

  if (s_islast && tid == 0){
    __threadfence();
    double tot = 0.0;
    for (int q = 0; q < GX; ++q){
      unsigned long long old = atomicExch((unsigned long long*)&g_part[q], 0ull);
      tot += __longlong_as_double((long long)old);
    }
    res[0] = (float)tot;
  }
}

extern "C" void kernel_launch(void* const* d_in, const int* in_sizes, int n_in,
                              void* d_out, int out_size){
  const float* outp = (const float*)d_in[0];
  const float* tgtp = (const float*)d_in[1];
  if (n_in >= 2 && in_sizes[0] < in_sizes[1]){
    const float* tmp = outp; outp = tgtp; tgtp = tmp;
  }
  region_kernel<<<dim3(GX, NB), TPB>>>(outp, tgtp, (float*)d_out);
}